// round 15
// baseline (speedup 1.0000x reference)
#include <cuda_runtime.h>
#include <cuda_fp16.h>
#include <cstdint>

#define MAXN 100000
#define MAXE 1600000
#define HID 128
#define CLS 40

// ---------------- scratch (static device memory, no allocations) ----------------
__device__ int      g_ideg_src[MAXN];
__device__ int      g_ideg_dst[MAXN];
__device__ float    g_csrc[MAXN];
__device__ float    g_cdst[MAXN];
__device__ int      g_roff[MAXN + 1];
__device__ int      g_cursor[MAXN];
__device__ int      g_bsums[128];
__device__ int      g_csr[MAXE];
__device__ __half   g_tmp [(size_t)MAXN * HID];     // GEMM output, fp16
__device__ __half   g_hbuf[(size_t)MAXN * HID];     // layer-1 activations, fp16
__device__ uint32_t g_w0[16384];                    // W0 packed fp16x2: 128 kp x 128
__device__ uint32_t g_w1[8192];                     // W1 packed fp16x2: 64 kp x 128

// ---------------- prep kernels ----------------
__global__ void degree_kernel(const int* __restrict__ src, const int* __restrict__ dst, int e) {
    int i = blockIdx.x * blockDim.x + threadIdx.x;
    if (i < e) {
        atomicAdd(&g_ideg_src[src[i]], 1);
        atomicAdd(&g_ideg_dst[dst[i]], 1);
    }
}

__global__ void scan1_kernel(const int* __restrict__ deg, int* __restrict__ out,
                             int* __restrict__ bsums, int n) {
    __shared__ int sm[1024];
    int i = blockIdx.x * 1024 + threadIdx.x;
    int v = (i < n) ? deg[i] : 0;
    sm[threadIdx.x] = v;
    __syncthreads();
    for (int off = 1; off < 1024; off <<= 1) {
        int t = (threadIdx.x >= off) ? sm[threadIdx.x - off] : 0;
        __syncthreads();
        sm[threadIdx.x] += t;
        __syncthreads();
    }
    if (i < n) out[i] = sm[threadIdx.x] - v;            // exclusive within block
    if (threadIdx.x == 1023) bsums[blockIdx.x] = sm[1023];
}

// scan3: per-block re-scan of bsums (merged scan2) + norms + cursor init
__global__ void scan3_kernel(int* __restrict__ roff, int* __restrict__ cursor,
                             const int* __restrict__ bsums, int n, int e, int nb) {
    __shared__ int smEx[128];
    {
        __shared__ int sm[128];
        int t = threadIdx.x;
        int v = 0;
        if (t < 128) { v = (t < nb) ? bsums[t] : 0; sm[t] = v; }
        __syncthreads();
        for (int off = 1; off < 128; off <<= 1) {
            int u = (t < 128 && t >= off) ? sm[t - off] : 0;
            __syncthreads();
            if (t < 128) sm[t] += u;
            __syncthreads();
        }
        if (t < 128) smEx[t] = sm[t] - v;               // exclusive block prefix
        __syncthreads();
    }
    int i = blockIdx.x * blockDim.x + threadIdx.x;
    if (i < n) {
        int v = roff[i] + smEx[i >> 10];
        roff[i] = v;
        cursor[i] = v;
        g_csrc[i] = rsqrtf(fmaxf((float)g_ideg_src[i], 1.f));
        g_cdst[i] = rsqrtf(fmaxf((float)g_ideg_dst[i], 1.f));
    }
    if (i == 0) roff[n] = e;
}

__global__ void csr_fill_kernel(const int* __restrict__ src, const int* __restrict__ dst,
                                int* __restrict__ cursor, int* __restrict__ csr, int e) {
    int i = blockIdx.x * blockDim.x + threadIdx.x;
    if (i < e) {
        int d = dst[i];
        int pos = atomicAdd(&cursor[d], 1);
        csr[pos] = src[i];
    }
}

// ---------------- weight pack (both layers, one launch) ----------------
__global__ void wpack_kernel(const float* __restrict__ W0, const float* __restrict__ W1) {
    int idx = blockIdx.x * blockDim.x + threadIdx.x;
    if (idx < 16384) {
        int kp = idx >> 7, n = idx & 127;
        __half2 h = __floats2half2_rn(W0[(size_t)(2 * kp) * 128 + n],
                                      W0[(size_t)(2 * kp + 1) * 128 + n]);
        g_w0[idx] = *reinterpret_cast<uint32_t*>(&h);
    } else if (idx < 24576) {
        int j = idx - 16384;
        int kp = j >> 7, n = j & 127;
        __half2 h = __floats2half2_rn(W1[(size_t)(2 * kp) * 128 + n],
                                      W1[(size_t)(2 * kp + 1) * 128 + n]);
        g_w1[j] = *reinterpret_cast<uint32_t*>(&h);
    }
}

#define MMA_FP16(d, a, b0v, b1v)                                                  \
    asm volatile("mma.sync.aligned.m16n8k16.row.col.f32.f16.f16.f32 "             \
                 "{%0,%1,%2,%3}, {%4,%5,%6,%7}, {%8,%9}, {%0,%1,%2,%3};"          \
                 : "+f"((d)[0]), "+f"((d)[1]), "+f"((d)[2]), "+f"((d)[3])         \
                 : "r"((a)[0]), "r"((a)[1]), "r"((a)[2]), "r"((a)[3]),            \
                   "r"(b0v), "r"(b1v));

#define AS_STRIDE 20
#define BS_STRIDE 136
#define AS_BUF    2560
#define BS_BUF    2176
#define GEMM_SMEM ((AS_BUF*2 + BS_BUF*2) * 4)   // 37888 bytes

#define CP_ASYNC16(dst_u32, src_ptr)                                              \
    asm volatile("cp.async.cg.shared.global [%0], [%1], 16;"                      \
                 :: "r"(dst_u32), "l"(src_ptr))
#define CP_COMMIT() asm volatile("cp.async.commit_group;" ::: "memory")
#define CP_WAIT0()  asm volatile("cp.async.wait_group 0;"  ::: "memory")

__device__ __forceinline__ float4 ld4(const float* A, size_t off) {
    return __ldg(reinterpret_cast<const float4*>(A + off));
}
__device__ __forceinline__ float4 ld4(const __half* A, size_t off) {
    uint2 u = __ldg(reinterpret_cast<const uint2*>(A + off));
    float2 a = __half22float2(*reinterpret_cast<__half2*>(&u.x));
    float2 b = __half22float2(*reinterpret_cast<__half2*>(&u.y));
    return make_float4(a.x, a.y, b.x, b.y);
}

// ---------------- double-buffered fp16 HMMA GEMM: C(fp16) = (A[M,K] @ W) [* rs[m]] ----
template<typename TA, bool SCALE>
__global__ __launch_bounds__(256, 2)
void gemm_fp16_kernel(const TA* __restrict__ A, const uint32_t* __restrict__ wp,
                      const float* __restrict__ rs, __half* __restrict__ C, int M, int K) {
    extern __shared__ uint32_t smem[];
    uint32_t* As = smem;
    uint32_t* Bs = smem + 2 * AS_BUF;

    const int tid  = threadIdx.x;
    const int warp = tid >> 5, lane = tid & 31;
    const int wm   = warp >> 1, wn = warp & 1;
    const int gid  = lane >> 2, tig = lane & 3;
    const int m0   = blockIdx.x * 128;
    const int nIter = K >> 5;

    float acc[2][8][4];
#pragma unroll
    for (int mt = 0; mt < 2; mt++)
#pragma unroll
        for (int nt = 0; nt < 8; nt++)
#pragma unroll
            for (int j = 0; j < 4; j++) acc[mt][nt][j] = 0.f;

    float4 aReg[4];

#define LD_A(k0)                                                                   \
    {                                                                              \
        _Pragma("unroll")                                                          \
        for (int l = 0; l < 4; l++) {                                              \
            int idx = tid + l * 256;                                               \
            int r = idx >> 3, c4 = idx & 7;                                        \
            aReg[l] = (m0 + r < M)                                                 \
                ? ld4(A, (size_t)(m0 + r) * K + (k0) + (c4 << 2))                  \
                : make_float4(0.f, 0.f, 0.f, 0.f);                                 \
        }                                                                          \
    }

#define ST_A(dst)                                                                  \
    {                                                                              \
        _Pragma("unroll")                                                          \
        for (int l = 0; l < 4; l++) {                                              \
            int idx = tid + l * 256;                                               \
            int r = idx >> 3, c4 = idx & 7;                                        \
            __half2 h0 = __floats2half2_rn(aReg[l].x, aReg[l].y);                  \
            __half2 h1 = __floats2half2_rn(aReg[l].z, aReg[l].w);                  \
            (dst)[r * AS_STRIDE + 2 * c4]     = *reinterpret_cast<uint32_t*>(&h0); \
            (dst)[r * AS_STRIDE + 2 * c4 + 1] = *reinterpret_cast<uint32_t*>(&h1); \
        }                                                                          \
    }

#define CP_B(k0p, dst)                                                             \
    {                                                                              \
        _Pragma("unroll")                                                          \
        for (int l = 0; l < 2; l++) {                                              \
            int idx = tid + l * 256;                                               \
            int kp = idx >> 5, n16 = idx & 31;                                     \
            uint32_t dh = (uint32_t)__cvta_generic_to_shared((dst) + kp * BS_STRIDE + n16 * 4); \
            CP_ASYNC16(dh, wp + ((k0p) + kp) * 128 + n16 * 4);                     \
        }                                                                          \
    }

    CP_B(0, Bs);
    CP_COMMIT();
    LD_A(0);
    ST_A(As);
    CP_WAIT0();
    __syncthreads();

    for (int it = 0; it < nIter; it++) {
        const int cur = it & 1, nxt = cur ^ 1;
        const bool more = (it + 1 < nIter);
        if (more) {
            LD_A((it + 1) << 5);
            CP_B((it + 1) << 4, Bs + nxt * BS_BUF);
            CP_COMMIT();
        }

        const uint32_t* aC = As + cur * AS_BUF;
        const uint32_t* bC = Bs + cur * BS_BUF;

#pragma unroll
        for (int kkp = 0; kkp < 16; kkp += 8) {
            uint32_t a[2][4];
#pragma unroll
            for (int mt = 0; mt < 2; mt++) {
                int rb = wm * 32 + mt * 16 + gid;
                int p0 = kkp + tig;
                a[mt][0] = aC[rb * AS_STRIDE + p0];
                a[mt][1] = aC[(rb + 8) * AS_STRIDE + p0];
                a[mt][2] = aC[rb * AS_STRIDE + p0 + 4];
                a[mt][3] = aC[(rb + 8) * AS_STRIDE + p0 + 4];
            }
#pragma unroll
            for (int nt = 0; nt < 8; nt++) {
                int cb = wn * 64 + nt * 8 + gid;
                uint32_t b0 = bC[(kkp + tig)     * BS_STRIDE + cb];
                uint32_t b1 = bC[(kkp + tig + 4) * BS_STRIDE + cb];
#pragma unroll
                for (int mt = 0; mt < 2; mt++) {
                    MMA_FP16(acc[mt][nt], a[mt], b0, b1);
                }
            }
        }

        if (more) {
            ST_A(As + nxt * AS_BUF);
            CP_WAIT0();
        }
        __syncthreads();
    }

#pragma unroll
    for (int mt = 0; mt < 2; mt++) {
        int r0 = m0 + wm * 32 + mt * 16 + gid;
        int r1 = r0 + 8;
        float s0 = 1.f, s1 = 1.f;
        if (SCALE) {
            if (r0 < M) s0 = __ldg(rs + r0);
            if (r1 < M) s1 = __ldg(rs + r1);
        }
#pragma unroll
        for (int nt = 0; nt < 8; nt++) {
            int c = wn * 64 + nt * 8 + 2 * tig;
            if (r0 < M) {
                __half2 o = __floats2half2_rn(acc[mt][nt][0] * s0, acc[mt][nt][1] * s0);
                *reinterpret_cast<__half2*>(C + (size_t)r0 * 128 + c) = o;
            }
            if (r1 < M) {
                __half2 o = __floats2half2_rn(acc[mt][nt][2] * s1, acc[mt][nt][3] * s1);
                *reinterpret_cast<__half2*>(C + (size_t)r1 * 128 + c) = o;
            }
        }
    }
#undef LD_A
#undef ST_A
#undef CP_B
}

// ---------------- gather body (shared by both spmm kernels) ----------------
template<bool SRC_SCALE>
__device__ __forceinline__ void spmm_gather(const __half* __restrict__ T,
                                            const int* __restrict__ csr,
                                            const float* __restrict__ csrc,
                                            int beg, int end, int half, int fl,
                                            float* acc) {
#pragma unroll
    for (int j = 0; j < 8; j++) acc[j] = 0.f;
    int i = beg;
    for (; i + 4 <= end; i += 4) {
        int s0 = __ldg(csr + i + half);
        int s1 = __ldg(csr + i + 2 + half);
        float c0 = SRC_SCALE ? __ldg(csrc + s0) : 1.f;
        float c1 = SRC_SCALE ? __ldg(csrc + s1) : 1.f;
        uint4 v0 = *(reinterpret_cast<const uint4*>(T + (size_t)s0 * 128) + fl);
        uint4 v1 = *(reinterpret_cast<const uint4*>(T + (size_t)s1 * 128) + fl);
        {
            float2 p0 = __half22float2(*reinterpret_cast<__half2*>(&v0.x));
            float2 p1 = __half22float2(*reinterpret_cast<__half2*>(&v0.y));
            float2 p2 = __half22float2(*reinterpret_cast<__half2*>(&v0.z));
            float2 p3 = __half22float2(*reinterpret_cast<__half2*>(&v0.w));
            acc[0] += p0.x * c0; acc[1] += p0.y * c0;
            acc[2] += p1.x * c0; acc[3] += p1.y * c0;
            acc[4] += p2.x * c0; acc[5] += p2.y * c0;
            acc[6] += p3.x * c0; acc[7] += p3.y * c0;
        }
        {
            float2 p0 = __half22float2(*reinterpret_cast<__half2*>(&v1.x));
            float2 p1 = __half22float2(*reinterpret_cast<__half2*>(&v1.y));
            float2 p2 = __half22float2(*reinterpret_cast<__half2*>(&v1.z));
            float2 p3 = __half22float2(*reinterpret_cast<__half2*>(&v1.w));
            acc[0] += p0.x * c1; acc[1] += p0.y * c1;
            acc[2] += p1.x * c1; acc[3] += p1.y * c1;
            acc[4] += p2.x * c1; acc[5] += p2.y * c1;
            acc[6] += p3.x * c1; acc[7] += p3.y * c1;
        }
    }
    for (; i < end; i += 2) {
        int e2 = i + half;
        if (e2 < end) {
            int s = __ldg(csr + e2);
            float c = SRC_SCALE ? __ldg(csrc + s) : 1.f;
            uint4 v = *(reinterpret_cast<const uint4*>(T + (size_t)s * 128) + fl);
            float2 p0 = __half22float2(*reinterpret_cast<__half2*>(&v.x));
            float2 p1 = __half22float2(*reinterpret_cast<__half2*>(&v.y));
            float2 p2 = __half22float2(*reinterpret_cast<__half2*>(&v.z));
            float2 p3 = __half22float2(*reinterpret_cast<__half2*>(&v.w));
            acc[0] += p0.x * c; acc[1] += p0.y * c;
            acc[2] += p1.x * c; acc[3] += p1.y * c;
            acc[4] += p2.x * c; acc[5] += p2.y * c;
            acc[6] += p3.x * c; acc[7] += p3.y * c;
        }
    }
#pragma unroll
    for (int j = 0; j < 8; j++)
        acc[j] += __shfl_xor_sync(0xffffffffu, acc[j], 16);
}

// ---------------- SpMM layer 0: out fp16, relu, c_src gathered ----------------
__global__ void spmm1_kernel(const __half* __restrict__ T, const int* __restrict__ csr,
                             const int* __restrict__ roff, const float* __restrict__ csrc,
                             const float* __restrict__ cdst, const float* __restrict__ bias,
                             __half* __restrict__ out, int n) {
    int w    = (blockIdx.x * blockDim.x + threadIdx.x) >> 5;
    int lane = threadIdx.x & 31;
    if (w >= n) return;
    const int half = lane >> 4, fl = lane & 15;
    int beg = __ldg(roff + w), end = __ldg(roff + w + 1);

    float acc[8];
    spmm_gather<true>(T, csr, csrc, beg, end, half, fl, acc);

    if (half == 0) {
        float c = __ldg(cdst + w);
        float4 b0 = *(reinterpret_cast<const float4*>(bias) + 2 * fl);
        float4 b1 = *(reinterpret_cast<const float4*>(bias) + 2 * fl + 1);
        float r0 = fmaxf(acc[0] * c + b0.x, 0.f), r1 = fmaxf(acc[1] * c + b0.y, 0.f);
        float r2 = fmaxf(acc[2] * c + b0.z, 0.f), r3 = fmaxf(acc[3] * c + b0.w, 0.f);
        float r4 = fmaxf(acc[4] * c + b1.x, 0.f), r5 = fmaxf(acc[5] * c + b1.y, 0.f);
        float r6 = fmaxf(acc[6] * c + b1.z, 0.f), r7 = fmaxf(acc[7] * c + b1.w, 0.f);
        __half2 h0 = __floats2half2_rn(r0, r1);
        __half2 h1 = __floats2half2_rn(r2, r3);
        __half2 h2 = __floats2half2_rn(r4, r5);
        __half2 h3 = __floats2half2_rn(r6, r7);
        uint4 u = make_uint4(*reinterpret_cast<uint32_t*>(&h0),
                             *reinterpret_cast<uint32_t*>(&h1),
                             *reinterpret_cast<uint32_t*>(&h2),
                             *reinterpret_cast<uint32_t*>(&h3));
        *(reinterpret_cast<uint4*>(out + (size_t)w * 128) + fl) = u;
    }
}

// ---------------- SpMM layer 1 + fused classifier head (256 threads) ----------------
// h = agg*c_dst + b1 -> out_h;  logits = relu(h) @ Wc + bc -> out_logits
// part[] kept in registers: all indices compile-time constant (5-way static write).
__global__ __launch_bounds__(256)
void spmm2_fused_kernel(const __half* __restrict__ T, const int* __restrict__ csr,
                        const int* __restrict__ roff, const float* __restrict__ cdst,
                        const float* __restrict__ bias, const float* __restrict__ Wc,
                        const float* __restrict__ bc,
                        float* __restrict__ out_h, float* __restrict__ out_logits, int n) {
    __shared__ float WcT[CLS][HID + 4];    // transposed, 16B-aligned rows

    // coalesced load over Wc's own [k][CLS] layout
    for (int i = threadIdx.x; i < HID * CLS; i += 256) {
        int k = i / CLS, c = i - k * CLS;
        WcT[c][k] = Wc[i];
    }
    __syncthreads();

    int w    = (blockIdx.x * blockDim.x + threadIdx.x) >> 5;
    int lane = threadIdx.x & 31;
    if (w >= n) return;
    const int half = lane >> 4, fl = lane & 15;
    int beg = __ldg(roff + w), end = __ldg(roff + w + 1);

    float acc[8];
    spmm_gather<false>(T, csr, nullptr, beg, end, half, fl, acc);

    // both halves hold the full 8-feat slice after the xor-16 reduce
    float c = __ldg(cdst + w);
    float4 b0 = *(reinterpret_cast<const float4*>(bias) + 2 * fl);
    float4 b1 = *(reinterpret_cast<const float4*>(bias) + 2 * fl + 1);
    float h0 = acc[0] * c + b0.x, h1 = acc[1] * c + b0.y;
    float h2 = acc[2] * c + b0.z, h3 = acc[3] * c + b0.w;
    float h4 = acc[4] * c + b1.x, h5 = acc[5] * c + b1.y;
    float h6 = acc[6] * c + b1.z, h7 = acc[7] * c + b1.w;

    if (half == 0) {
        float* o = out_h + (size_t)w * 128 + fl * 8;
        *reinterpret_cast<float4*>(o)     = make_float4(h0, h1, h2, h3);
        *reinterpret_cast<float4*>(o + 4) = make_float4(h4, h5, h6, h7);
    }

    h0 = fmaxf(h0, 0.f); h1 = fmaxf(h1, 0.f); h2 = fmaxf(h2, 0.f); h3 = fmaxf(h3, 0.f);
    h4 = fmaxf(h4, 0.f); h5 = fmaxf(h5, 0.f); h6 = fmaxf(h6, 0.f); h7 = fmaxf(h7, 0.f);

    // half 0 -> classes [0,20), half 1 -> classes [20,40)
    const int cbase = half * 20;
    float part[20];
#pragma unroll
    for (int cc = 0; cc < 20; cc++) {
        const float* wr = &WcT[cbase + cc][fl * 8];
        float4 wa = *reinterpret_cast<const float4*>(wr);
        float4 wb = *reinterpret_cast<const float4*>(wr + 4);
        part[cc] = h0 * wa.x + h1 * wa.y + h2 * wa.z + h3 * wa.w
                 + h4 * wb.x + h5 * wb.y + h6 * wb.z + h7 * wb.w;
    }
#pragma unroll
    for (int off = 1; off < 16; off <<= 1)
#pragma unroll
        for (int cc = 0; cc < 20; cc++)
            part[cc] += __shfl_xor_sync(0xffffffffu, part[cc], off);

    if (fl < 5) {
        // static indexing only — keeps part[] in registers
        float o0, o1, o2, o3;
        switch (fl) {
            case 0: o0 = part[0];  o1 = part[1];  o2 = part[2];  o3 = part[3];  break;
            case 1: o0 = part[4];  o1 = part[5];  o2 = part[6];  o3 = part[7];  break;
            case 2: o0 = part[8];  o1 = part[9];  o2 = part[10]; o3 = part[11]; break;
            case 3: o0 = part[12]; o1 = part[13]; o2 = part[14]; o3 = part[15]; break;
            default: o0 = part[16]; o1 = part[17]; o2 = part[18]; o3 = part[19]; break;
        }
        float4 bcv = __ldg(reinterpret_cast<const float4*>(bc) + (cbase >> 2) + fl);
        float4 o = make_float4(o0 + bcv.x, o1 + bcv.y, o2 + bcv.z, o3 + bcv.w);
        *reinterpret_cast<float4*>(out_logits + (size_t)w * CLS + cbase + fl * 4) = o;
    }
}

// ---------------- launch ----------------
extern "C" void kernel_launch(void* const* d_in, const int* in_sizes, int n_in,
                              void* d_out, int out_size) {
    const float* x   = (const float*)d_in[0];
    const int*   src = (const int*)d_in[1];
    const int*   dst = (const int*)d_in[2];
    const float* W0  = (const float*)d_in[3];
    const float* b0  = (const float*)d_in[4];
    const float* W1  = (const float*)d_in[5];
    const float* b1  = (const float*)d_in[6];
    const float* Wc  = (const float*)d_in[7];
    const float* bc  = (const float*)d_in[8];

    const int n = in_sizes[0] / 256;
    const int e = in_sizes[1];

    int *ideg_s, *ideg_d, *roff, *cursor, *bsums, *csr;
    float *csrc, *cdst;
    __half *tmp, *hbuf;
    uint32_t *w0, *w1;
    cudaGetSymbolAddress((void**)&ideg_s, g_ideg_src);
    cudaGetSymbolAddress((void**)&ideg_d, g_ideg_dst);
    cudaGetSymbolAddress((void**)&roff,   g_roff);
    cudaGetSymbolAddress((void**)&cursor, g_cursor);
    cudaGetSymbolAddress((void**)&bsums,  g_bsums);
    cudaGetSymbolAddress((void**)&csr,    g_csr);
    cudaGetSymbolAddress((void**)&csrc,   g_csrc);
    cudaGetSymbolAddress((void**)&cdst,   g_cdst);
    cudaGetSymbolAddress((void**)&tmp,    g_tmp);
    cudaGetSymbolAddress((void**)&hbuf,   g_hbuf);
    cudaGetSymbolAddress((void**)&w0,     g_w0);
    cudaGetSymbolAddress((void**)&w1,     g_w1);

    float* out_h      = (float*)d_out;
    float* out_logits = out_h + (size_t)n * HID;

    static cudaStream_t s_side = nullptr;
    static cudaEvent_t  ev_fork = nullptr, ev_join = nullptr;
    if (s_side == nullptr) {
        cudaStreamCreateWithFlags(&s_side, cudaStreamNonBlocking);
        cudaEventCreateWithFlags(&ev_fork, cudaEventDisableTiming);
        cudaEventCreateWithFlags(&ev_join, cudaEventDisableTiming);
        cudaFuncSetAttribute((const void*)gemm_fp16_kernel<float, false>,
                             cudaFuncAttributeMaxDynamicSharedMemorySize, GEMM_SMEM);
        cudaFuncSetAttribute((const void*)gemm_fp16_kernel<__half, true>,
                             cudaFuncAttributeMaxDynamicSharedMemorySize, GEMM_SMEM);
    }

    const int nb = (n + 1023) / 1024;
    const int gblocks = (n + 127) / 128;
    const int sblocks = (int)(((size_t)n * 32 + 255) / 256);

    // ---- fork: CSR/degree chain on side stream; weight pack + GEMM1 on main ----
    cudaEventRecord(ev_fork, 0);
    cudaStreamWaitEvent(s_side, ev_fork, 0);

    cudaMemsetAsync(ideg_s, 0, (size_t)n * sizeof(int), s_side);
    cudaMemsetAsync(ideg_d, 0, (size_t)n * sizeof(int), s_side);
    degree_kernel<<<(e + 255) / 256, 256, 0, s_side>>>(src, dst, e);
    scan1_kernel<<<nb, 1024, 0, s_side>>>(ideg_d, roff, bsums, n);
    scan3_kernel<<<(n + 255) / 256, 256, 0, s_side>>>(roff, cursor, bsums, n, e, nb);
    csr_fill_kernel<<<(e + 255) / 256, 256, 0, s_side>>>(src, dst, cursor, csr, e);

    wpack_kernel<<<96, 256>>>(W0, W1);
    gemm_fp16_kernel<float, false><<<gblocks, 256, GEMM_SMEM>>>(x, w0, nullptr, tmp, n, 256);

    // ---- join ----
    cudaEventRecord(ev_join, s_side);
    cudaStreamWaitEvent(0, ev_join, 0);

    // layer 0 aggregate (+bias+relu), fp16 out
    spmm1_kernel<<<sblocks, 256>>>(tmp, csr, roff, csrc, cdst, b0, hbuf, n);

    // layer 1: GEMM applies c_src in epilogue; spmm2 fuses h-out + classifier head
    gemm_fp16_kernel<__half, true><<<gblocks, 256, GEMM_SMEM>>>(hbuf, w1, csrc, tmp, n, 128);
    spmm2_fused_kernel<<<sblocks, 256>>>(tmp, csr, roff, cdst, b1, Wc, bc,
                                         out_h, out_logits, n);
}

// round 16
// speedup vs baseline: 1.2763x; 1.2763x over previous
#include <cuda_runtime.h>
#include <cuda_fp16.h>
#include <cstdint>

#define MAXN 100000
#define MAXE 1600000
#define HID 128
#define CLS 40

// ---------------- scratch (static device memory, no allocations) ----------------
__device__ int      g_ideg_src[MAXN];
__device__ int      g_ideg_dst[MAXN];
__device__ float    g_csrc[MAXN];
__device__ float    g_cdst[MAXN];
__device__ int      g_roff[MAXN + 1];
__device__ int      g_cursor[MAXN];
__device__ int      g_bsums[128];
__device__ int      g_csr[MAXE];
__device__ __half   g_tmp [(size_t)MAXN * HID];     // GEMM output, fp16
__device__ __half   g_hbuf[(size_t)MAXN * HID];     // layer-1 activations, fp16
__device__ uint32_t g_w0[16384];                    // W0 packed fp16x2: 128 kp x 128
__device__ uint32_t g_w1[8192];                     // W1 packed fp16x2: 64 kp x 128

// ---------------- prep kernels ----------------
__global__ void degree_kernel(const int* __restrict__ src, const int* __restrict__ dst, int e) {
    int i = blockIdx.x * blockDim.x + threadIdx.x;
    if (i < e) {
        atomicAdd(&g_ideg_src[src[i]], 1);
        atomicAdd(&g_ideg_dst[dst[i]], 1);
    }
}

__global__ void scan1_kernel(const int* __restrict__ deg, int* __restrict__ out,
                             int* __restrict__ bsums, int n) {
    __shared__ int sm[1024];
    int i = blockIdx.x * 1024 + threadIdx.x;
    int v = (i < n) ? deg[i] : 0;
    sm[threadIdx.x] = v;
    __syncthreads();
    for (int off = 1; off < 1024; off <<= 1) {
        int t = (threadIdx.x >= off) ? sm[threadIdx.x - off] : 0;
        __syncthreads();
        sm[threadIdx.x] += t;
        __syncthreads();
    }
    if (i < n) out[i] = sm[threadIdx.x] - v;            // exclusive within block
    if (threadIdx.x == 1023) bsums[blockIdx.x] = sm[1023];
}

// scan3: per-block re-scan of bsums (merged scan2) + norms + cursor init
__global__ void scan3_kernel(int* __restrict__ roff, int* __restrict__ cursor,
                             const int* __restrict__ bsums, int n, int e, int nb) {
    __shared__ int smEx[128];
    {
        __shared__ int sm[128];
        int t = threadIdx.x;
        int v = 0;
        if (t < 128) { v = (t < nb) ? bsums[t] : 0; sm[t] = v; }
        __syncthreads();
        for (int off = 1; off < 128; off <<= 1) {
            int u = (t < 128 && t >= off) ? sm[t - off] : 0;
            __syncthreads();
            if (t < 128) sm[t] += u;
            __syncthreads();
        }
        if (t < 128) smEx[t] = sm[t] - v;               // exclusive block prefix
        __syncthreads();
    }
    int i = blockIdx.x * blockDim.x + threadIdx.x;
    if (i < n) {
        int v = roff[i] + smEx[i >> 10];
        roff[i] = v;
        cursor[i] = v;
        g_csrc[i] = rsqrtf(fmaxf((float)g_ideg_src[i], 1.f));
        g_cdst[i] = rsqrtf(fmaxf((float)g_ideg_dst[i], 1.f));
    }
    if (i == 0) roff[n] = e;
}

__global__ void csr_fill_kernel(const int* __restrict__ src, const int* __restrict__ dst,
                                int* __restrict__ cursor, int* __restrict__ csr, int e) {
    int i = blockIdx.x * blockDim.x + threadIdx.x;
    if (i < e) {
        int d = dst[i];
        int pos = atomicAdd(&cursor[d], 1);
        csr[pos] = src[i];
    }
}

// ---------------- weight pack (both layers, one launch) ----------------
__global__ void wpack_kernel(const float* __restrict__ W0, const float* __restrict__ W1) {
    int idx = blockIdx.x * blockDim.x + threadIdx.x;
    if (idx < 16384) {
        int kp = idx >> 7, n = idx & 127;
        __half2 h = __floats2half2_rn(W0[(size_t)(2 * kp) * 128 + n],
                                      W0[(size_t)(2 * kp + 1) * 128 + n]);
        g_w0[idx] = *reinterpret_cast<uint32_t*>(&h);
    } else if (idx < 24576) {
        int j = idx - 16384;
        int kp = j >> 7, n = j & 127;
        __half2 h = __floats2half2_rn(W1[(size_t)(2 * kp) * 128 + n],
                                      W1[(size_t)(2 * kp + 1) * 128 + n]);
        g_w1[j] = *reinterpret_cast<uint32_t*>(&h);
    }
}

#define MMA_FP16(d, a, b0v, b1v)                                                  \
    asm volatile("mma.sync.aligned.m16n8k16.row.col.f32.f16.f16.f32 "             \
                 "{%0,%1,%2,%3}, {%4,%5,%6,%7}, {%8,%9}, {%0,%1,%2,%3};"          \
                 : "+f"((d)[0]), "+f"((d)[1]), "+f"((d)[2]), "+f"((d)[3])         \
                 : "r"((a)[0]), "r"((a)[1]), "r"((a)[2]), "r"((a)[3]),            \
                   "r"(b0v), "r"(b1v));

#define AS_STRIDE 20
#define BS_STRIDE 136
#define AS_BUF    2560
#define BS_BUF    2176
#define GEMM_SMEM ((AS_BUF*2 + BS_BUF*2) * 4)   // 37888 bytes

#define CP_ASYNC16(dst_u32, src_ptr)                                              \
    asm volatile("cp.async.cg.shared.global [%0], [%1], 16;"                      \
                 :: "r"(dst_u32), "l"(src_ptr))
#define CP_COMMIT() asm volatile("cp.async.commit_group;" ::: "memory")
#define CP_WAIT0()  asm volatile("cp.async.wait_group 0;"  ::: "memory")

__device__ __forceinline__ float4 ld4(const float* A, size_t off) {
    return __ldg(reinterpret_cast<const float4*>(A + off));
}
__device__ __forceinline__ float4 ld4(const __half* A, size_t off) {
    uint2 u = __ldg(reinterpret_cast<const uint2*>(A + off));
    float2 a = __half22float2(*reinterpret_cast<__half2*>(&u.x));
    float2 b = __half22float2(*reinterpret_cast<__half2*>(&u.y));
    return make_float4(a.x, a.y, b.x, b.y);
}

// ---------------- double-buffered fp16 HMMA GEMM: C(fp16) = (A[M,K] @ W) [* rs[m]] ----
template<typename TA, bool SCALE>
__global__ __launch_bounds__(256, 2)
void gemm_fp16_kernel(const TA* __restrict__ A, const uint32_t* __restrict__ wp,
                      const float* __restrict__ rs, __half* __restrict__ C, int M, int K) {
    extern __shared__ uint32_t smem[];
    uint32_t* As = smem;
    uint32_t* Bs = smem + 2 * AS_BUF;

    const int tid  = threadIdx.x;
    const int warp = tid >> 5, lane = tid & 31;
    const int wm   = warp >> 1, wn = warp & 1;
    const int gid  = lane >> 2, tig = lane & 3;
    const int m0   = blockIdx.x * 128;
    const int nIter = K >> 5;

    float acc[2][8][4];
#pragma unroll
    for (int mt = 0; mt < 2; mt++)
#pragma unroll
        for (int nt = 0; nt < 8; nt++)
#pragma unroll
            for (int j = 0; j < 4; j++) acc[mt][nt][j] = 0.f;

    float4 aReg[4];

#define LD_A(k0)                                                                   \
    {                                                                              \
        _Pragma("unroll")                                                          \
        for (int l = 0; l < 4; l++) {                                              \
            int idx = tid + l * 256;                                               \
            int r = idx >> 3, c4 = idx & 7;                                        \
            aReg[l] = (m0 + r < M)                                                 \
                ? ld4(A, (size_t)(m0 + r) * K + (k0) + (c4 << 2))                  \
                : make_float4(0.f, 0.f, 0.f, 0.f);                                 \
        }                                                                          \
    }

#define ST_A(dst)                                                                  \
    {                                                                              \
        _Pragma("unroll")                                                          \
        for (int l = 0; l < 4; l++) {                                              \
            int idx = tid + l * 256;                                               \
            int r = idx >> 3, c4 = idx & 7;                                        \
            __half2 h0 = __floats2half2_rn(aReg[l].x, aReg[l].y);                  \
            __half2 h1 = __floats2half2_rn(aReg[l].z, aReg[l].w);                  \
            (dst)[r * AS_STRIDE + 2 * c4]     = *reinterpret_cast<uint32_t*>(&h0); \
            (dst)[r * AS_STRIDE + 2 * c4 + 1] = *reinterpret_cast<uint32_t*>(&h1); \
        }                                                                          \
    }

#define CP_B(k0p, dst)                                                             \
    {                                                                              \
        _Pragma("unroll")                                                          \
        for (int l = 0; l < 2; l++) {                                              \
            int idx = tid + l * 256;                                               \
            int kp = idx >> 5, n16 = idx & 31;                                     \
            uint32_t dh = (uint32_t)__cvta_generic_to_shared((dst) + kp * BS_STRIDE + n16 * 4); \
            CP_ASYNC16(dh, wp + ((k0p) + kp) * 128 + n16 * 4);                     \
        }                                                                          \
    }

    CP_B(0, Bs);
    CP_COMMIT();
    LD_A(0);
    ST_A(As);
    CP_WAIT0();
    __syncthreads();

    for (int it = 0; it < nIter; it++) {
        const int cur = it & 1, nxt = cur ^ 1;
        const bool more = (it + 1 < nIter);
        if (more) {
            LD_A((it + 1) << 5);
            CP_B((it + 1) << 4, Bs + nxt * BS_BUF);
            CP_COMMIT();
        }

        const uint32_t* aC = As + cur * AS_BUF;
        const uint32_t* bC = Bs + cur * BS_BUF;

#pragma unroll
        for (int kkp = 0; kkp < 16; kkp += 8) {
            uint32_t a[2][4];
#pragma unroll
            for (int mt = 0; mt < 2; mt++) {
                int rb = wm * 32 + mt * 16 + gid;
                int p0 = kkp + tig;
                a[mt][0] = aC[rb * AS_STRIDE + p0];
                a[mt][1] = aC[(rb + 8) * AS_STRIDE + p0];
                a[mt][2] = aC[rb * AS_STRIDE + p0 + 4];
                a[mt][3] = aC[(rb + 8) * AS_STRIDE + p0 + 4];
            }
#pragma unroll
            for (int nt = 0; nt < 8; nt++) {
                int cb = wn * 64 + nt * 8 + gid;
                uint32_t b0 = bC[(kkp + tig)     * BS_STRIDE + cb];
                uint32_t b1 = bC[(kkp + tig + 4) * BS_STRIDE + cb];
#pragma unroll
                for (int mt = 0; mt < 2; mt++) {
                    MMA_FP16(acc[mt][nt], a[mt], b0, b1);
                }
            }
        }

        if (more) {
            ST_A(As + nxt * AS_BUF);
            CP_WAIT0();
        }
        __syncthreads();
    }

#pragma unroll
    for (int mt = 0; mt < 2; mt++) {
        int r0 = m0 + wm * 32 + mt * 16 + gid;
        int r1 = r0 + 8;
        float s0 = 1.f, s1 = 1.f;
        if (SCALE) {
            if (r0 < M) s0 = __ldg(rs + r0);
            if (r1 < M) s1 = __ldg(rs + r1);
        }
#pragma unroll
        for (int nt = 0; nt < 8; nt++) {
            int c = wn * 64 + nt * 8 + 2 * tig;
            if (r0 < M) {
                __half2 o = __floats2half2_rn(acc[mt][nt][0] * s0, acc[mt][nt][1] * s0);
                *reinterpret_cast<__half2*>(C + (size_t)r0 * 128 + c) = o;
            }
            if (r1 < M) {
                __half2 o = __floats2half2_rn(acc[mt][nt][2] * s1, acc[mt][nt][3] * s1);
                *reinterpret_cast<__half2*>(C + (size_t)r1 * 128 + c) = o;
            }
        }
    }
#undef LD_A
#undef ST_A
#undef CP_B
}

// ---------------- CSR SpMM, split-warp: 16 lanes per row, 2 edges per LDG.128 ----
// out[v] = (sum_{s in N(v)} [c_src[s]] * T[s]) * c_dst[v] + b   (optional relu)
template<typename OutT, bool RELU, bool SRC_SCALE>
__global__ void spmm_csr_kernel(const __half* __restrict__ T, const int* __restrict__ csr,
                                const int* __restrict__ roff, const float* __restrict__ csrc,
                                const float* __restrict__ cdst,
                                const float* __restrict__ bias, OutT* __restrict__ out, int n) {
    int w    = (blockIdx.x * blockDim.x + threadIdx.x) >> 5;
    int lane = threadIdx.x & 31;
    if (w >= n) return;
    const int half = lane >> 4;         // which edge of the pair
    const int fl   = lane & 15;         // feature lane: feats [fl*8, fl*8+8)
    int beg = __ldg(roff + w), end = __ldg(roff + w + 1);

    float acc[8];
#pragma unroll
    for (int j = 0; j < 8; j++) acc[j] = 0.f;

    int i = beg;
    for (; i + 4 <= end; i += 4) {
        int s0 = __ldg(csr + i + half);
        int s1 = __ldg(csr + i + 2 + half);
        float c0 = SRC_SCALE ? __ldg(csrc + s0) : 1.f;
        float c1 = SRC_SCALE ? __ldg(csrc + s1) : 1.f;
        uint4 v0 = *(reinterpret_cast<const uint4*>(T + (size_t)s0 * 128) + fl);
        uint4 v1 = *(reinterpret_cast<const uint4*>(T + (size_t)s1 * 128) + fl);
        {
            float2 p0 = __half22float2(*reinterpret_cast<__half2*>(&v0.x));
            float2 p1 = __half22float2(*reinterpret_cast<__half2*>(&v0.y));
            float2 p2 = __half22float2(*reinterpret_cast<__half2*>(&v0.z));
            float2 p3 = __half22float2(*reinterpret_cast<__half2*>(&v0.w));
            acc[0] += p0.x * c0; acc[1] += p0.y * c0;
            acc[2] += p1.x * c0; acc[3] += p1.y * c0;
            acc[4] += p2.x * c0; acc[5] += p2.y * c0;
            acc[6] += p3.x * c0; acc[7] += p3.y * c0;
        }
        {
            float2 p0 = __half22float2(*reinterpret_cast<__half2*>(&v1.x));
            float2 p1 = __half22float2(*reinterpret_cast<__half2*>(&v1.y));
            float2 p2 = __half22float2(*reinterpret_cast<__half2*>(&v1.z));
            float2 p3 = __half22float2(*reinterpret_cast<__half2*>(&v1.w));
            acc[0] += p0.x * c1; acc[1] += p0.y * c1;
            acc[2] += p1.x * c1; acc[3] += p1.y * c1;
            acc[4] += p2.x * c1; acc[5] += p2.y * c1;
            acc[6] += p3.x * c1; acc[7] += p3.y * c1;
        }
    }
    for (; i < end; i += 2) {
        int e2 = i + half;
        if (e2 < end) {
            int s = __ldg(csr + e2);
            float c = SRC_SCALE ? __ldg(csrc + s) : 1.f;
            uint4 v = *(reinterpret_cast<const uint4*>(T + (size_t)s * 128) + fl);
            float2 p0 = __half22float2(*reinterpret_cast<__half2*>(&v.x));
            float2 p1 = __half22float2(*reinterpret_cast<__half2*>(&v.y));
            float2 p2 = __half22float2(*reinterpret_cast<__half2*>(&v.z));
            float2 p3 = __half22float2(*reinterpret_cast<__half2*>(&v.w));
            acc[0] += p0.x * c; acc[1] += p0.y * c;
            acc[2] += p1.x * c; acc[3] += p1.y * c;
            acc[4] += p2.x * c; acc[5] += p2.y * c;
            acc[6] += p3.x * c; acc[7] += p3.y * c;
        }
    }
#pragma unroll
    for (int j = 0; j < 8; j++)
        acc[j] += __shfl_xor_sync(0xffffffffu, acc[j], 16);

    float c = __ldg(cdst + w);
    if (half == 0) {
        float4 b0 = *(reinterpret_cast<const float4*>(bias) + 2 * fl);
        float4 b1 = *(reinterpret_cast<const float4*>(bias) + 2 * fl + 1);
        float r0 = acc[0] * c + b0.x, r1 = acc[1] * c + b0.y;
        float r2 = acc[2] * c + b0.z, r3 = acc[3] * c + b0.w;
        float r4 = acc[4] * c + b1.x, r5 = acc[5] * c + b1.y;
        float r6 = acc[6] * c + b1.z, r7 = acc[7] * c + b1.w;
        if (RELU) {
            r0 = fmaxf(r0, 0.f); r1 = fmaxf(r1, 0.f); r2 = fmaxf(r2, 0.f); r3 = fmaxf(r3, 0.f);
            r4 = fmaxf(r4, 0.f); r5 = fmaxf(r5, 0.f); r6 = fmaxf(r6, 0.f); r7 = fmaxf(r7, 0.f);
        }
        if (sizeof(OutT) == 2) {
            __half2 h0 = __floats2half2_rn(r0, r1);
            __half2 h1 = __floats2half2_rn(r2, r3);
            __half2 h2 = __floats2half2_rn(r4, r5);
            __half2 h3 = __floats2half2_rn(r6, r7);
            uint4 u = make_uint4(*reinterpret_cast<uint32_t*>(&h0),
                                 *reinterpret_cast<uint32_t*>(&h1),
                                 *reinterpret_cast<uint32_t*>(&h2),
                                 *reinterpret_cast<uint32_t*>(&h3));
            *(reinterpret_cast<uint4*>(reinterpret_cast<__half*>(out) + (size_t)w * 128) + fl) = u;
        } else {
            float* o = reinterpret_cast<float*>(out) + (size_t)w * 128 + fl * 8;
            *reinterpret_cast<float4*>(o)     = make_float4(r0, r1, r2, r3);
            *reinterpret_cast<float4*>(o + 4) = make_float4(r4, r5, r6, r7);
        }
    }
}

// ---------------- final: logits = relu(h) @ Wc + bc ----------------
__global__ void final_kernel(const float* __restrict__ h, const float* __restrict__ Wc,
                             const float* __restrict__ bc, float* __restrict__ out_logits, int n) {
    __shared__ float hs[32][HID + 1];
    __shared__ float Wcs[HID][CLS];
    __shared__ float bcs[CLS];

    const int tid = threadIdx.x;
    const int n0  = blockIdx.x * 32;

    for (int i = tid; i < HID * CLS; i += 256) Wcs[i / CLS][i % CLS] = Wc[i];
    if (tid < CLS) bcs[tid] = bc[tid];

    for (int i = tid; i < 32 * HID; i += 256) {
        int r = i >> 7, c = i & 127;
        int g = n0 + r;
        hs[r][c] = (g < n) ? fmaxf(h[(size_t)g * HID + c], 0.f) : 0.f;
    }
    __syncthreads();

    int r  = tid & 31;
    int cg = tid >> 5;
    int g  = n0 + r;
    if (g < n) {
        float acc[5];
#pragma unroll
        for (int j = 0; j < 5; j++) acc[j] = bcs[cg * 5 + j];
        for (int k = 0; k < HID; k++) {
            float a = hs[r][k];
#pragma unroll
            for (int j = 0; j < 5; j++) acc[j] = fmaf(a, Wcs[k][cg * 5 + j], acc[j]);
        }
#pragma unroll
        for (int j = 0; j < 5; j++) out_logits[(size_t)g * CLS + cg * 5 + j] = acc[j];
    }
}

// ---------------- launch ----------------
extern "C" void kernel_launch(void* const* d_in, const int* in_sizes, int n_in,
                              void* d_out, int out_size) {
    const float* x   = (const float*)d_in[0];
    const int*   src = (const int*)d_in[1];
    const int*   dst = (const int*)d_in[2];
    const float* W0  = (const float*)d_in[3];
    const float* b0  = (const float*)d_in[4];
    const float* W1  = (const float*)d_in[5];
    const float* b1  = (const float*)d_in[6];
    const float* Wc  = (const float*)d_in[7];
    const float* bc  = (const float*)d_in[8];

    const int n = in_sizes[0] / 256;
    const int e = in_sizes[1];

    int *ideg_s, *ideg_d, *roff, *cursor, *bsums, *csr;
    float *csrc, *cdst;
    __half *tmp, *hbuf;
    uint32_t *w0, *w1;
    cudaGetSymbolAddress((void**)&ideg_s, g_ideg_src);
    cudaGetSymbolAddress((void**)&ideg_d, g_ideg_dst);
    cudaGetSymbolAddress((void**)&roff,   g_roff);
    cudaGetSymbolAddress((void**)&cursor, g_cursor);
    cudaGetSymbolAddress((void**)&bsums,  g_bsums);
    cudaGetSymbolAddress((void**)&csr,    g_csr);
    cudaGetSymbolAddress((void**)&csrc,   g_csrc);
    cudaGetSymbolAddress((void**)&cdst,   g_cdst);
    cudaGetSymbolAddress((void**)&tmp,    g_tmp);
    cudaGetSymbolAddress((void**)&hbuf,   g_hbuf);
    cudaGetSymbolAddress((void**)&w0,     g_w0);
    cudaGetSymbolAddress((void**)&w1,     g_w1);

    float* out_h      = (float*)d_out;
    float* out_logits = out_h + (size_t)n * HID;

    static cudaStream_t s_side = nullptr;
    static cudaEvent_t  ev_fork = nullptr, ev_join = nullptr;
    if (s_side == nullptr) {
        cudaStreamCreateWithFlags(&s_side, cudaStreamNonBlocking);
        cudaEventCreateWithFlags(&ev_fork, cudaEventDisableTiming);
        cudaEventCreateWithFlags(&ev_join, cudaEventDisableTiming);
        cudaFuncSetAttribute((const void*)gemm_fp16_kernel<float, false>,
                             cudaFuncAttributeMaxDynamicSharedMemorySize, GEMM_SMEM);
        cudaFuncSetAttribute((const void*)gemm_fp16_kernel<__half, true>,
                             cudaFuncAttributeMaxDynamicSharedMemorySize, GEMM_SMEM);
    }

    const int nb = (n + 1023) / 1024;
    const int gblocks = (n + 127) / 128;
    const int sblocks = (int)(((size_t)n * 32 + 255) / 256);

    // ---- fork: CSR/degree chain on side stream; weight pack + GEMM1 on main ----
    cudaEventRecord(ev_fork, 0);
    cudaStreamWaitEvent(s_side, ev_fork, 0);

    cudaMemsetAsync(ideg_s, 0, (size_t)n * sizeof(int), s_side);
    cudaMemsetAsync(ideg_d, 0, (size_t)n * sizeof(int), s_side);
    degree_kernel<<<(e + 255) / 256, 256, 0, s_side>>>(src, dst, e);
    scan1_kernel<<<nb, 1024, 0, s_side>>>(ideg_d, roff, bsums, n);
    scan3_kernel<<<(n + 255) / 256, 256, 0, s_side>>>(roff, cursor, bsums, n, e, nb);
    csr_fill_kernel<<<(e + 255) / 256, 256, 0, s_side>>>(src, dst, cursor, csr, e);

    wpack_kernel<<<96, 256>>>(W0, W1);
    gemm_fp16_kernel<float, false><<<gblocks, 256, GEMM_SMEM>>>(x, w0, nullptr, tmp, n, 256);

    // ---- join ----
    cudaEventRecord(ev_join, s_side);
    cudaStreamWaitEvent(0, ev_join, 0);

    // layer 0 aggregate (+bias+relu); c_src gathered per edge
    spmm_csr_kernel<__half, true, true><<<sblocks, 256>>>(tmp, csr, roff, csrc, cdst, b0, hbuf, n);

    // layer 1: GEMM applies c_src[r] in epilogue -> spmm2 skips csrc gather
    gemm_fp16_kernel<__half, true><<<gblocks, 256, GEMM_SMEM>>>(hbuf, w1, csrc, tmp, n, 128);
    spmm_csr_kernel<float, false, false><<<sblocks, 256>>>(tmp, csr, roff, nullptr, cdst, b1, out_h, n);

    final_kernel<<<(n + 31) / 32, 256>>>(out_h, Wc, bc, out_logits, n);
}

// round 17
// speedup vs baseline: 1.8296x; 1.4335x over previous
#include <cuda_runtime.h>
#include <cuda_fp16.h>
#include <cstdint>

#define MAXN 100000
#define MAXE 1600000
#define HID 128
#define CLS 40

// ---------------- scratch (static device memory, no allocations) ----------------
__device__ int      g_ideg_src[MAXN];
__device__ int      g_ideg_dst[MAXN];
__device__ float    g_csrc[MAXN];
__device__ float    g_cdst[MAXN];
__device__ int      g_roff[MAXN + 1];
__device__ int      g_cursor[MAXN];
__device__ int      g_bsums[128];
__device__ int      g_csr[MAXE];
__device__ __half   g_tmp [(size_t)MAXN * HID];     // GEMM output, fp16
__device__ __half   g_hbuf[(size_t)MAXN * HID];     // layer-1 activations, fp16
__device__ uint32_t g_w0[16384];                    // W0 packed fp16x2: 128 kp x 128
__device__ uint32_t g_w1[8192];                     // W1 packed fp16x2: 64 kp x 128
__device__ uint32_t g_wc[2560];                     // Wc packed fp16x2: 64 kp x 40

// ---------------- prep kernels ----------------
__global__ void degree_kernel(const int* __restrict__ src, const int* __restrict__ dst, int e) {
    int i = blockIdx.x * blockDim.x + threadIdx.x;
    if (i < e) {
        atomicAdd(&g_ideg_src[src[i]], 1);
        atomicAdd(&g_ideg_dst[dst[i]], 1);
    }
}

__global__ void scan1_kernel(const int* __restrict__ deg, int* __restrict__ out,
                             int* __restrict__ bsums, int n) {
    __shared__ int sm[1024];
    int i = blockIdx.x * 1024 + threadIdx.x;
    int v = (i < n) ? deg[i] : 0;
    sm[threadIdx.x] = v;
    __syncthreads();
    for (int off = 1; off < 1024; off <<= 1) {
        int t = (threadIdx.x >= off) ? sm[threadIdx.x - off] : 0;
        __syncthreads();
        sm[threadIdx.x] += t;
        __syncthreads();
    }
    if (i < n) out[i] = sm[threadIdx.x] - v;
    if (threadIdx.x == 1023) bsums[blockIdx.x] = sm[1023];
}

__global__ void scan3_kernel(int* __restrict__ roff, int* __restrict__ cursor,
                             const int* __restrict__ bsums, int n, int e, int nb) {
    __shared__ int smEx[128];
    {
        __shared__ int sm[128];
        int t = threadIdx.x;
        int v = 0;
        if (t < 128) { v = (t < nb) ? bsums[t] : 0; sm[t] = v; }
        __syncthreads();
        for (int off = 1; off < 128; off <<= 1) {
            int u = (t < 128 && t >= off) ? sm[t - off] : 0;
            __syncthreads();
            if (t < 128) sm[t] += u;
            __syncthreads();
        }
        if (t < 128) smEx[t] = sm[t] - v;
        __syncthreads();
    }
    int i = blockIdx.x * blockDim.x + threadIdx.x;
    if (i < n) {
        int v = roff[i] + smEx[i >> 10];
        roff[i] = v;
        cursor[i] = v;
        g_csrc[i] = rsqrtf(fmaxf((float)g_ideg_src[i], 1.f));
        g_cdst[i] = rsqrtf(fmaxf((float)g_ideg_dst[i], 1.f));
    }
    if (i == 0) roff[n] = e;
}

__global__ void csr_fill_kernel(const int* __restrict__ src, const int* __restrict__ dst,
                                int* __restrict__ cursor, int* __restrict__ csr, int e) {
    int i = blockIdx.x * blockDim.x + threadIdx.x;
    if (i < e) {
        int d = dst[i];
        int pos = atomicAdd(&cursor[d], 1);
        csr[pos] = src[i];
    }
}

// ---------------- weight pack (W0, W1, Wc in one launch) ----------------
__global__ void wpack_kernel(const float* __restrict__ W0, const float* __restrict__ W1,
                             const float* __restrict__ Wc) {
    int idx = blockIdx.x * blockDim.x + threadIdx.x;
    if (idx < 16384) {
        int kp = idx >> 7, n = idx & 127;
        __half2 h = __floats2half2_rn(W0[(size_t)(2 * kp) * 128 + n],
                                      W0[(size_t)(2 * kp + 1) * 128 + n]);
        g_w0[idx] = *reinterpret_cast<uint32_t*>(&h);
    } else if (idx < 24576) {
        int j = idx - 16384;
        int kp = j >> 7, n = j & 127;
        __half2 h = __floats2half2_rn(W1[(size_t)(2 * kp) * 128 + n],
                                      W1[(size_t)(2 * kp + 1) * 128 + n]);
        g_w1[j] = *reinterpret_cast<uint32_t*>(&h);
    } else if (idx < 27136) {
        int j = idx - 24576;              // 0..2559 : (kp, c)
        int kp = j / 40, c = j - kp * 40;
        __half2 h = __floats2half2_rn(Wc[(size_t)(2 * kp) * CLS + c],
                                      Wc[(size_t)(2 * kp + 1) * CLS + c]);
        g_wc[j] = *reinterpret_cast<uint32_t*>(&h);
    }
}

#define MMA_FP16(d, a, b0v, b1v)                                                  \
    asm volatile("mma.sync.aligned.m16n8k16.row.col.f32.f16.f16.f32 "             \
                 "{%0,%1,%2,%3}, {%4,%5,%6,%7}, {%8,%9}, {%0,%1,%2,%3};"          \
                 : "+f"((d)[0]), "+f"((d)[1]), "+f"((d)[2]), "+f"((d)[3])         \
                 : "r"((a)[0]), "r"((a)[1]), "r"((a)[2]), "r"((a)[3]),            \
                   "r"(b0v), "r"(b1v));

#define AS_STRIDE 20
#define BS_STRIDE 136
#define AS_BUF    2560
#define BS_BUF    2176
#define GEMM_SMEM ((AS_BUF*2 + BS_BUF*2) * 4)   // 37888 bytes

#define CP_ASYNC16(dst_u32, src_ptr)                                              \
    asm volatile("cp.async.cg.shared.global [%0], [%1], 16;"                      \
                 :: "r"(dst_u32), "l"(src_ptr))
#define CP_COMMIT() asm volatile("cp.async.commit_group;" ::: "memory")
#define CP_WAIT0()  asm volatile("cp.async.wait_group 0;"  ::: "memory")

__device__ __forceinline__ float4 ld4(const float* A, size_t off) {
    return __ldg(reinterpret_cast<const float4*>(A + off));
}
__device__ __forceinline__ float4 ld4(const __half* A, size_t off) {
    uint2 u = __ldg(reinterpret_cast<const uint2*>(A + off));
    float2 a = __half22float2(*reinterpret_cast<__half2*>(&u.x));
    float2 b = __half22float2(*reinterpret_cast<__half2*>(&u.y));
    return make_float4(a.x, a.y, b.x, b.y);
}

// ---------------- double-buffered fp16 HMMA GEMM: C(fp16) = (A[M,K] @ W) [* rs[m]] ----
template<typename TA, bool SCALE>
__global__ __launch_bounds__(256, 2)
void gemm_fp16_kernel(const TA* __restrict__ A, const uint32_t* __restrict__ wp,
                      const float* __restrict__ rs, __half* __restrict__ C, int M, int K) {
    extern __shared__ uint32_t smem[];
    uint32_t* As = smem;
    uint32_t* Bs = smem + 2 * AS_BUF;

    const int tid  = threadIdx.x;
    const int warp = tid >> 5, lane = tid & 31;
    const int wm   = warp >> 1, wn = warp & 1;
    const int gid  = lane >> 2, tig = lane & 3;
    const int m0   = blockIdx.x * 128;
    const int nIter = K >> 5;

    float acc[2][8][4];
#pragma unroll
    for (int mt = 0; mt < 2; mt++)
#pragma unroll
        for (int nt = 0; nt < 8; nt++)
#pragma unroll
            for (int j = 0; j < 4; j++) acc[mt][nt][j] = 0.f;

    float4 aReg[4];

#define LD_A(k0)                                                                   \
    {                                                                              \
        _Pragma("unroll")                                                          \
        for (int l = 0; l < 4; l++) {                                              \
            int idx = tid + l * 256;                                               \
            int r = idx >> 3, c4 = idx & 7;                                        \
            aReg[l] = (m0 + r < M)                                                 \
                ? ld4(A, (size_t)(m0 + r) * K + (k0) + (c4 << 2))                  \
                : make_float4(0.f, 0.f, 0.f, 0.f);                                 \
        }                                                                          \
    }

#define ST_A(dst)                                                                  \
    {                                                                              \
        _Pragma("unroll")                                                          \
        for (int l = 0; l < 4; l++) {                                              \
            int idx = tid + l * 256;                                               \
            int r = idx >> 3, c4 = idx & 7;                                        \
            __half2 h0 = __floats2half2_rn(aReg[l].x, aReg[l].y);                  \
            __half2 h1 = __floats2half2_rn(aReg[l].z, aReg[l].w);                  \
            (dst)[r * AS_STRIDE + 2 * c4]     = *reinterpret_cast<uint32_t*>(&h0); \
            (dst)[r * AS_STRIDE + 2 * c4 + 1] = *reinterpret_cast<uint32_t*>(&h1); \
        }                                                                          \
    }

#define CP_B(k0p, dst)                                                             \
    {                                                                              \
        _Pragma("unroll")                                                          \
        for (int l = 0; l < 2; l++) {                                              \
            int idx = tid + l * 256;                                               \
            int kp = idx >> 5, n16 = idx & 31;                                     \
            uint32_t dh = (uint32_t)__cvta_generic_to_shared((dst) + kp * BS_STRIDE + n16 * 4); \
            CP_ASYNC16(dh, wp + ((k0p) + kp) * 128 + n16 * 4);                     \
        }                                                                          \
    }

    CP_B(0, Bs);
    CP_COMMIT();
    LD_A(0);
    ST_A(As);
    CP_WAIT0();
    __syncthreads();

    for (int it = 0; it < nIter; it++) {
        const int cur = it & 1, nxt = cur ^ 1;
        const bool more = (it + 1 < nIter);
        if (more) {
            LD_A((it + 1) << 5);
            CP_B((it + 1) << 4, Bs + nxt * BS_BUF);
            CP_COMMIT();
        }

        const uint32_t* aC = As + cur * AS_BUF;
        const uint32_t* bC = Bs + cur * BS_BUF;

#pragma unroll
        for (int kkp = 0; kkp < 16; kkp += 8) {
            uint32_t a[2][4];
#pragma unroll
            for (int mt = 0; mt < 2; mt++) {
                int rb = wm * 32 + mt * 16 + gid;
                int p0 = kkp + tig;
                a[mt][0] = aC[rb * AS_STRIDE + p0];
                a[mt][1] = aC[(rb + 8) * AS_STRIDE + p0];
                a[mt][2] = aC[rb * AS_STRIDE + p0 + 4];
                a[mt][3] = aC[(rb + 8) * AS_STRIDE + p0 + 4];
            }
#pragma unroll
            for (int nt = 0; nt < 8; nt++) {
                int cb = wn * 64 + nt * 8 + gid;
                uint32_t b0 = bC[(kkp + tig)     * BS_STRIDE + cb];
                uint32_t b1 = bC[(kkp + tig + 4) * BS_STRIDE + cb];
#pragma unroll
                for (int mt = 0; mt < 2; mt++) {
                    MMA_FP16(acc[mt][nt], a[mt], b0, b1);
                }
            }
        }

        if (more) {
            ST_A(As + nxt * AS_BUF);
            CP_WAIT0();
        }
        __syncthreads();
    }

#pragma unroll
    for (int mt = 0; mt < 2; mt++) {
        int r0 = m0 + wm * 32 + mt * 16 + gid;
        int r1 = r0 + 8;
        float s0 = 1.f, s1 = 1.f;
        if (SCALE) {
            if (r0 < M) s0 = __ldg(rs + r0);
            if (r1 < M) s1 = __ldg(rs + r1);
        }
#pragma unroll
        for (int nt = 0; nt < 8; nt++) {
            int c = wn * 64 + nt * 8 + 2 * tig;
            if (r0 < M) {
                __half2 o = __floats2half2_rn(acc[mt][nt][0] * s0, acc[mt][nt][1] * s0);
                *reinterpret_cast<__half2*>(C + (size_t)r0 * 128 + c) = o;
            }
            if (r1 < M) {
                __half2 o = __floats2half2_rn(acc[mt][nt][2] * s1, acc[mt][nt][3] * s1);
                *reinterpret_cast<__half2*>(C + (size_t)r1 * 128 + c) = o;
            }
        }
    }
#undef LD_A
#undef ST_A
#undef CP_B
}

// ---------------- CSR SpMM, split-warp: 16 lanes per row, 2 edges per LDG.128 ----
template<typename OutT, bool RELU, bool SRC_SCALE>
__global__ void spmm_csr_kernel(const __half* __restrict__ T, const int* __restrict__ csr,
                                const int* __restrict__ roff, const float* __restrict__ csrc,
                                const float* __restrict__ cdst,
                                const float* __restrict__ bias, OutT* __restrict__ out, int n) {
    int w    = (blockIdx.x * blockDim.x + threadIdx.x) >> 5;
    int lane = threadIdx.x & 31;
    if (w >= n) return;
    const int half = lane >> 4;
    const int fl   = lane & 15;
    int beg = __ldg(roff + w), end = __ldg(roff + w + 1);

    float acc[8];
#pragma unroll
    for (int j = 0; j < 8; j++) acc[j] = 0.f;

    int i = beg;
    for (; i + 4 <= end; i += 4) {
        int s0 = __ldg(csr + i + half);
        int s1 = __ldg(csr + i + 2 + half);
        float c0 = SRC_SCALE ? __ldg(csrc + s0) : 1.f;
        float c1 = SRC_SCALE ? __ldg(csrc + s1) : 1.f;
        uint4 v0 = *(reinterpret_cast<const uint4*>(T + (size_t)s0 * 128) + fl);
        uint4 v1 = *(reinterpret_cast<const uint4*>(T + (size_t)s1 * 128) + fl);
        {
            float2 p0 = __half22float2(*reinterpret_cast<__half2*>(&v0.x));
            float2 p1 = __half22float2(*reinterpret_cast<__half2*>(&v0.y));
            float2 p2 = __half22float2(*reinterpret_cast<__half2*>(&v0.z));
            float2 p3 = __half22float2(*reinterpret_cast<__half2*>(&v0.w));
            acc[0] += p0.x * c0; acc[1] += p0.y * c0;
            acc[2] += p1.x * c0; acc[3] += p1.y * c0;
            acc[4] += p2.x * c0; acc[5] += p2.y * c0;
            acc[6] += p3.x * c0; acc[7] += p3.y * c0;
        }
        {
            float2 p0 = __half22float2(*reinterpret_cast<__half2*>(&v1.x));
            float2 p1 = __half22float2(*reinterpret_cast<__half2*>(&v1.y));
            float2 p2 = __half22float2(*reinterpret_cast<__half2*>(&v1.z));
            float2 p3 = __half22float2(*reinterpret_cast<__half2*>(&v1.w));
            acc[0] += p0.x * c1; acc[1] += p0.y * c1;
            acc[2] += p1.x * c1; acc[3] += p1.y * c1;
            acc[4] += p2.x * c1; acc[5] += p2.y * c1;
            acc[6] += p3.x * c1; acc[7] += p3.y * c1;
        }
    }
    for (; i < end; i += 2) {
        int e2 = i + half;
        if (e2 < end) {
            int s = __ldg(csr + e2);
            float c = SRC_SCALE ? __ldg(csrc + s) : 1.f;
            uint4 v = *(reinterpret_cast<const uint4*>(T + (size_t)s * 128) + fl);
            float2 p0 = __half22float2(*reinterpret_cast<__half2*>(&v.x));
            float2 p1 = __half22float2(*reinterpret_cast<__half2*>(&v.y));
            float2 p2 = __half22float2(*reinterpret_cast<__half2*>(&v.z));
            float2 p3 = __half22float2(*reinterpret_cast<__half2*>(&v.w));
            acc[0] += p0.x * c; acc[1] += p0.y * c;
            acc[2] += p1.x * c; acc[3] += p1.y * c;
            acc[4] += p2.x * c; acc[5] += p2.y * c;
            acc[6] += p3.x * c; acc[7] += p3.y * c;
        }
    }
#pragma unroll
    for (int j = 0; j < 8; j++)
        acc[j] += __shfl_xor_sync(0xffffffffu, acc[j], 16);

    float c = __ldg(cdst + w);
    if (half == 0) {
        float4 b0 = *(reinterpret_cast<const float4*>(bias) + 2 * fl);
        float4 b1 = *(reinterpret_cast<const float4*>(bias) + 2 * fl + 1);
        float r0 = acc[0] * c + b0.x, r1 = acc[1] * c + b0.y;
        float r2 = acc[2] * c + b0.z, r3 = acc[3] * c + b0.w;
        float r4 = acc[4] * c + b1.x, r5 = acc[5] * c + b1.y;
        float r6 = acc[6] * c + b1.z, r7 = acc[7] * c + b1.w;
        if (RELU) {
            r0 = fmaxf(r0, 0.f); r1 = fmaxf(r1, 0.f); r2 = fmaxf(r2, 0.f); r3 = fmaxf(r3, 0.f);
            r4 = fmaxf(r4, 0.f); r5 = fmaxf(r5, 0.f); r6 = fmaxf(r6, 0.f); r7 = fmaxf(r7, 0.f);
        }
        if (sizeof(OutT) == 2) {
            __half2 h0 = __floats2half2_rn(r0, r1);
            __half2 h1 = __floats2half2_rn(r2, r3);
            __half2 h2 = __floats2half2_rn(r4, r5);
            __half2 h3 = __floats2half2_rn(r6, r7);
            uint4 u = make_uint4(*reinterpret_cast<uint32_t*>(&h0),
                                 *reinterpret_cast<uint32_t*>(&h1),
                                 *reinterpret_cast<uint32_t*>(&h2),
                                 *reinterpret_cast<uint32_t*>(&h3));
            *(reinterpret_cast<uint4*>(reinterpret_cast<__half*>(out) + (size_t)w * 128) + fl) = u;
        } else {
            float* o = reinterpret_cast<float*>(out) + (size_t)w * 128 + fl * 8;
            *reinterpret_cast<float4*>(o)     = make_float4(r0, r1, r2, r3);
            *reinterpret_cast<float4*>(o + 4) = make_float4(r4, r5, r6, r7);
        }
    }
}

// ---------------- HMMA classifier head: logits = relu(h) @ Wc + bc ----------------
// Block = 128 rows, 8 warps x 16 rows. h staged relu->fp16 in smem (stride-68 u32),
// Wc pre-packed fp16 k-pairs ([kp][40], stride-40 conflict-free B frags).
#define HS_STRIDE 68
__global__ __launch_bounds__(256)
void head_kernel(const float* __restrict__ h, const uint32_t* __restrict__ wcp,
                 const float* __restrict__ bc, float* __restrict__ out_logits, int M) {
    __shared__ uint32_t hs[128 * HS_STRIDE];   // 34816 B
    __shared__ uint32_t wcs[64 * 40];          // 10240 B
    __shared__ float    bcs[CLS];

    const int tid  = threadIdx.x;
    const int warp = tid >> 5, lane = tid & 31;
    const int gid  = lane >> 2, tig = lane & 3;
    const int m0   = blockIdx.x * 128;

    // stage h rows (relu -> fp16 pairs), 4096 float4s
#pragma unroll
    for (int l = 0; l < 16; l++) {
        int idx = tid + l * 256;               // (row, float4)
        int r = idx >> 5, c4 = idx & 31;
        float4 v = make_float4(0.f, 0.f, 0.f, 0.f);
        if (m0 + r < M) v = __ldg(reinterpret_cast<const float4*>(h + (size_t)(m0 + r) * HID + (c4 << 2)));
        __half2 h0 = __floats2half2_rn(fmaxf(v.x, 0.f), fmaxf(v.y, 0.f));
        __half2 h1 = __floats2half2_rn(fmaxf(v.z, 0.f), fmaxf(v.w, 0.f));
        hs[r * HS_STRIDE + 2 * c4]     = *reinterpret_cast<uint32_t*>(&h0);
        hs[r * HS_STRIDE + 2 * c4 + 1] = *reinterpret_cast<uint32_t*>(&h1);
    }
    for (int i = tid; i < 2560; i += 256) wcs[i] = wcp[i];
    if (tid < CLS) bcs[tid] = bc[tid];
    __syncthreads();

    float acc[5][4];
#pragma unroll
    for (int nt = 0; nt < 5; nt++)
#pragma unroll
        for (int j = 0; j < 4; j++) acc[nt][j] = 0.f;

#pragma unroll
    for (int ks = 0; ks < 8; ks++) {
        uint32_t a[4];
        int rb = warp * 16 + gid;
        int p0 = ks * 8 + tig;
        a[0] = hs[rb * HS_STRIDE + p0];
        a[1] = hs[(rb + 8) * HS_STRIDE + p0];
        a[2] = hs[rb * HS_STRIDE + p0 + 4];
        a[3] = hs[(rb + 8) * HS_STRIDE + p0 + 4];
#pragma unroll
        for (int nt = 0; nt < 5; nt++) {
            uint32_t b0 = wcs[(ks * 8 + tig)     * 40 + nt * 8 + gid];
            uint32_t b1 = wcs[(ks * 8 + tig + 4) * 40 + nt * 8 + gid];
            MMA_FP16(acc[nt], a, b0, b1);
        }
    }

    // epilogue: rows (gid, gid+8), cols 2*tig..2*tig+1 per n-tile
    int r0 = m0 + warp * 16 + gid;
    int r1 = r0 + 8;
#pragma unroll
    for (int nt = 0; nt < 5; nt++) {
        int c = nt * 8 + 2 * tig;
        float bx = bcs[c], by = bcs[c + 1];
        if (r0 < M) {
            float2 o = make_float2(acc[nt][0] + bx, acc[nt][1] + by);
            *reinterpret_cast<float2*>(out_logits + (size_t)r0 * CLS + c) = o;
        }
        if (r1 < M) {
            float2 o = make_float2(acc[nt][2] + bx, acc[nt][3] + by);
            *reinterpret_cast<float2*>(out_logits + (size_t)r1 * CLS + c) = o;
        }
    }
}

// ---------------- launch ----------------
extern "C" void kernel_launch(void* const* d_in, const int* in_sizes, int n_in,
                              void* d_out, int out_size) {
    const float* x   = (const float*)d_in[0];
    const int*   src = (const int*)d_in[1];
    const int*   dst = (const int*)d_in[2];
    const float* W0  = (const float*)d_in[3];
    const float* b0  = (const float*)d_in[4];
    const float* W1  = (const float*)d_in[5];
    const float* b1  = (const float*)d_in[6];
    const float* Wc  = (const float*)d_in[7];
    const float* bc  = (const float*)d_in[8];

    const int n = in_sizes[0] / 256;
    const int e = in_sizes[1];

    int *ideg_s, *ideg_d, *roff, *cursor, *bsums, *csr;
    float *csrc, *cdst;
    __half *tmp, *hbuf;
    uint32_t *w0, *w1, *wc;
    cudaGetSymbolAddress((void**)&ideg_s, g_ideg_src);
    cudaGetSymbolAddress((void**)&ideg_d, g_ideg_dst);
    cudaGetSymbolAddress((void**)&roff,   g_roff);
    cudaGetSymbolAddress((void**)&cursor, g_cursor);
    cudaGetSymbolAddress((void**)&bsums,  g_bsums);
    cudaGetSymbolAddress((void**)&csr,    g_csr);
    cudaGetSymbolAddress((void**)&csrc,   g_csrc);
    cudaGetSymbolAddress((void**)&cdst,   g_cdst);
    cudaGetSymbolAddress((void**)&tmp,    g_tmp);
    cudaGetSymbolAddress((void**)&hbuf,   g_hbuf);
    cudaGetSymbolAddress((void**)&w0,     g_w0);
    cudaGetSymbolAddress((void**)&w1,     g_w1);
    cudaGetSymbolAddress((void**)&wc,     g_wc);

    float* out_h      = (float*)d_out;
    float* out_logits = out_h + (size_t)n * HID;

    static cudaStream_t s_side = nullptr;
    static cudaEvent_t  ev_fork = nullptr, ev_join = nullptr;
    if (s_side == nullptr) {
        cudaStreamCreateWithFlags(&s_side, cudaStreamNonBlocking);
        cudaEventCreateWithFlags(&ev_fork, cudaEventDisableTiming);
        cudaEventCreateWithFlags(&ev_join, cudaEventDisableTiming);
        cudaFuncSetAttribute((const void*)gemm_fp16_kernel<float, false>,
                             cudaFuncAttributeMaxDynamicSharedMemorySize, GEMM_SMEM);
        cudaFuncSetAttribute((const void*)gemm_fp16_kernel<__half, true>,
                             cudaFuncAttributeMaxDynamicSharedMemorySize, GEMM_SMEM);
    }

    const int nb = (n + 1023) / 1024;
    const int gblocks = (n + 127) / 128;
    const int sblocks = (int)(((size_t)n * 32 + 255) / 256);

    // ---- fork: CSR/degree chain on side stream; weight pack + GEMM1 on main ----
    cudaEventRecord(ev_fork, 0);
    cudaStreamWaitEvent(s_side, ev_fork, 0);

    cudaMemsetAsync(ideg_s, 0, (size_t)n * sizeof(int), s_side);
    cudaMemsetAsync(ideg_d, 0, (size_t)n * sizeof(int), s_side);
    degree_kernel<<<(e + 255) / 256, 256, 0, s_side>>>(src, dst, e);
    scan1_kernel<<<nb, 1024, 0, s_side>>>(ideg_d, roff, bsums, n);
    scan3_kernel<<<(n + 255) / 256, 256, 0, s_side>>>(roff, cursor, bsums, n, e, nb);
    csr_fill_kernel<<<(e + 255) / 256, 256, 0, s_side>>>(src, dst, cursor, csr, e);

    wpack_kernel<<<106, 256>>>(W0, W1, Wc);
    gemm_fp16_kernel<float, false><<<gblocks, 256, GEMM_SMEM>>>(x, w0, nullptr, tmp, n, 256);

    // ---- join ----
    cudaEventRecord(ev_join, s_side);
    cudaStreamWaitEvent(0, ev_join, 0);

    // layer 0 aggregate (+bias+relu); c_src gathered per edge
    spmm_csr_kernel<__half, true, true><<<sblocks, 256>>>(tmp, csr, roff, csrc, cdst, b0, hbuf, n);

    // layer 1: GEMM applies c_src[r] in epilogue -> spmm2 skips csrc gather
    gemm_fp16_kernel<__half, true><<<gblocks, 256, GEMM_SMEM>>>(hbuf, w1, csrc, tmp, n, 128);
    spmm_csr_kernel<float, false, false><<<sblocks, 256>>>(tmp, csr, roff, nullptr, cdst, b1, out_h, n);

    // HMMA classifier head
    head_kernel<<<gblocks, 256>>>(out_h, wc, bc, out_logits, n);
}